// round 15
// baseline (speedup 1.0000x reference)
#include <cuda_runtime.h>

#define BATCH 16
#define CHAN  3
#define HH 512
#define WW 512
#define ROWS_PER_THREAD 4
#define NTHREADS 256
#define DELTA2 1e-6f

__global__ void zero_out_kernel(float* out, int n) {
    int i = blockIdx.x * blockDim.x + threadIdx.x;
    if (i < n) out[i] = 0.0f;
}

__global__ __launch_bounds__(NTHREADS, 4)   // 1024 thr/SM, 64-reg budget (R9 config)
void photometric_kernel(const float* __restrict__ frame1,
                        const float* __restrict__ frame2,
                        const float* __restrict__ flow,
                        float* __restrict__ out) {
    const int HW = HH * WW;
    const int x  = blockIdx.x * NTHREADS + threadIdx.x;   // lanes: 32 consecutive x
    const int y0 = blockIdx.y * ROWS_PER_THREAD;
    const int b  = blockIdx.z;

    const float* f1b = frame1 + (size_t)b * CHAN * HW;
    const float* f2b = frame2 + (size_t)b * CHAN * HW;
    const float* flx = flow + (size_t)(b * 2 + 0) * HW;
    const float* fly = flow + (size_t)(b * 2 + 1) * HW;
    const float scale = (float)(WW - 1) / (float)WW;      // W == H
    const float xf = (float)x;

    // ---- phase 1: flow loads + coords (independent chains) ----
    int idx00[ROWS_PER_THREAD];
    float wxa[ROWS_PER_THREAD], wya[ROWS_PER_THREAD];

    #pragma unroll
    for (int r = 0; r < ROWS_PER_THREAD; r++) {
        const int y  = y0 + r;
        const int hw = y * WW + x;
        const float fx = __ldg(flx + hw);
        const float fy = __ldg(fly + hw);

        float ix = (xf + fx) * scale;
        float iy = ((float)y + fy) * scale;
        ix = fminf(fmaxf(ix, 0.0f), (float)(WW - 1));
        iy = fminf(fmaxf(iy, 0.0f), (float)(HH - 1));

        const int x0 = min((int)ix, WW - 2);
        const int yi = min((int)iy, HH - 2);
        wxa[r] = ix - (float)x0;
        wya[r] = iy - (float)yi;
        idx00[r] = yi * WW + x0;
    }

    // ---- phase 2: aligned float2 pair-gathers + math ----
    float acc = 0.0f;

    #pragma unroll
    for (int r = 0; r < ROWS_PER_THREAD; r++) {
        const int hw  = (y0 + r) * WW + x;
        const int i00 = idx00[r];
        const float wx = wxa[r];
        const float wy = wya[r];
        const int e   = i00 & ~1;          // 8B-aligned, same row (W even)
        const bool odd = (i00 & 1) != 0;

        #pragma unroll
        for (int c = 0; c < CHAN; c++) {
            const float* p = f2b + (size_t)c * HW;
            const float2 t0 = __ldg((const float2*)(p + e));        // row y0
            const float2 t1 = __ldg((const float2*)(p + e + WW));   // row y0+1
            float v00, v01, v10, v11;
            if (odd) {                                              // ~50% of lanes
                const float2 u0 = __ldg((const float2*)(p + e + 2));
                const float2 u1 = __ldg((const float2*)(p + e + 2 + WW));
                v00 = t0.y; v01 = u0.x;
                v10 = t1.y; v11 = u1.x;
            } else {
                v00 = t0.x; v01 = t0.y;
                v10 = t1.x; v11 = t1.y;
            }
            const float top = fmaf(v01 - v00, wx, v00);
            const float bot = fmaf(v11 - v10, wx, v10);
            const float wv  = fmaf(bot - top, wy, top);
            const float d = __ldg(f1b + c * HW + hw) - wv;
            acc += __powf(fmaf(d, d, DELTA2), 0.45f);
        }
    }

    // ---- block reduction ----
    #pragma unroll
    for (int off = 16; off > 0; off >>= 1)
        acc += __shfl_down_sync(0xFFFFFFFFu, acc, off);

    __shared__ float warp_sums[NTHREADS / 32];
    const int lane = threadIdx.x & 31;
    const int wid  = threadIdx.x >> 5;
    if (lane == 0) warp_sums[wid] = acc;
    __syncthreads();

    if (wid == 0) {
        float s = (lane < (NTHREADS / 32)) ? warp_sums[lane] : 0.0f;
        #pragma unroll
        for (int off = 4; off > 0; off >>= 1)
            s += __shfl_down_sync(0xFFFFFFFFu, s, off);
        if (lane == 0) atomicAdd(out, s);
    }
}

extern "C" void kernel_launch(void* const* d_in, const int* in_sizes, int n_in,
                              void* d_out, int out_size) {
    const float* frame1 = (const float*)d_in[0];
    const float* frame2 = (const float*)d_in[1];
    const float* flow   = (const float*)d_in[2];
    float* out = (float*)d_out;

    zero_out_kernel<<<(out_size + 255) / 256, 256>>>(out, out_size);

    dim3 grid(WW / NTHREADS, HH / ROWS_PER_THREAD, BATCH);  // 2 x 128 x 16
    photometric_kernel<<<grid, NTHREADS>>>(frame1, frame2, flow, out);
}

// round 16
// speedup vs baseline: 1.2976x; 1.2976x over previous
#include <cuda_runtime.h>

#define BATCH 16
#define CHAN  3
#define HH 512
#define WW 512
#define ROWS_PER_THREAD 4
#define NTHREADS 256
#define DELTA2 1e-6f

__global__ void zero_out_kernel(float* out, int n) {
    int i = blockIdx.x * blockDim.x + threadIdx.x;
    if (i < n) out[i] = 0.0f;
}

__global__ __launch_bounds__(NTHREADS, 4)   // 1024 thr/SM, 64-reg budget (R9 config)
void photometric_kernel(const float* __restrict__ frame1,
                        const float* __restrict__ frame2,
                        const float* __restrict__ flow,
                        float* __restrict__ out) {
    const int HW = HH * WW;
    const int x  = blockIdx.x * NTHREADS + threadIdx.x;   // lanes: 32 consecutive x
    const int y0 = blockIdx.y * ROWS_PER_THREAD;
    const int b  = blockIdx.z;

    const float* f1b = frame1 + (size_t)b * CHAN * HW;
    const float* f2b = frame2 + (size_t)b * CHAN * HW;
    const float* flx = flow + (size_t)(b * 2 + 0) * HW;
    const float* fly = flow + (size_t)(b * 2 + 1) * HW;
    const float scale = (float)(WW - 1) / (float)WW;      // W == H
    const float xf = (float)x;

    // ---- phase 1: flow loads (streaming, evict-first) + coords ----
    int idx00[ROWS_PER_THREAD];
    float wxa[ROWS_PER_THREAD], wya[ROWS_PER_THREAD];

    #pragma unroll
    for (int r = 0; r < ROWS_PER_THREAD; r++) {
        const int y  = y0 + r;
        const int hw = y * WW + x;
        const float fx = __ldcs(flx + hw);     // single-use: don't pollute L1
        const float fy = __ldcs(fly + hw);

        float ix = (xf + fx) * scale;
        float iy = ((float)y + fy) * scale;
        ix = fminf(fmaxf(ix, 0.0f), (float)(WW - 1));
        iy = fminf(fmaxf(iy, 0.0f), (float)(HH - 1));

        // x0 = min(floor(ix), W-2); wx = ix - x0 (exact incl. boundary)
        const int x0 = min((int)ix, WW - 2);
        const int yi = min((int)iy, HH - 2);
        wxa[r] = ix - (float)x0;
        wya[r] = iy - (float)yi;
        idx00[r] = yi * WW + x0;
    }

    // ---- phase 2: scalar gathers (cached: frame2 has reuse) + math ----
    float acc = 0.0f;

    #pragma unroll
    for (int r = 0; r < ROWS_PER_THREAD; r++) {
        const int hw  = (y0 + r) * WW + x;
        const int i00 = idx00[r];
        const float wx = wxa[r];
        const float wy = wya[r];

        #pragma unroll
        for (int c = 0; c < CHAN; c++) {
            const float* p = f2b + (size_t)c * HW + i00;
            const float v00 = __ldg(p);
            const float v01 = __ldg(p + 1);
            const float v10 = __ldg(p + WW);
            const float v11 = __ldg(p + WW + 1);
            const float top = fmaf(v01 - v00, wx, v00);
            const float bot = fmaf(v11 - v10, wx, v10);
            const float wv  = fmaf(bot - top, wy, top);
            const float d = __ldcs(f1b + c * HW + hw) - wv;   // single-use stream
            acc += __powf(fmaf(d, d, DELTA2), 0.45f);
        }
    }

    // ---- block reduction ----
    #pragma unroll
    for (int off = 16; off > 0; off >>= 1)
        acc += __shfl_down_sync(0xFFFFFFFFu, acc, off);

    __shared__ float warp_sums[NTHREADS / 32];
    const int lane = threadIdx.x & 31;
    const int wid  = threadIdx.x >> 5;
    if (lane == 0) warp_sums[wid] = acc;
    __syncthreads();

    if (wid == 0) {
        float s = (lane < (NTHREADS / 32)) ? warp_sums[lane] : 0.0f;
        #pragma unroll
        for (int off = 4; off > 0; off >>= 1)
            s += __shfl_down_sync(0xFFFFFFFFu, s, off);
        if (lane == 0) atomicAdd(out, s);
    }
}

extern "C" void kernel_launch(void* const* d_in, const int* in_sizes, int n_in,
                              void* d_out, int out_size) {
    const float* frame1 = (const float*)d_in[0];
    const float* frame2 = (const float*)d_in[1];
    const float* flow   = (const float*)d_in[2];
    float* out = (float*)d_out;

    zero_out_kernel<<<(out_size + 255) / 256, 256>>>(out, out_size);

    dim3 grid(WW / NTHREADS, HH / ROWS_PER_THREAD, BATCH);  // 2 x 128 x 16
    photometric_kernel<<<grid, NTHREADS>>>(frame1, frame2, flow, out);
}